// round 5
// baseline (speedup 1.0000x reference)
#include <cuda_runtime.h>
#include <cstdint>

// ---------------------------------------------------------------------------
// FPNAttentionV2: fused conv1x1 batches + conv3x3/s2, BHWC outputs.
// TF32 mma.sync m16n8k8. CTA tile 128 px x 128 och x BK=32, 256 threads,
// 8 warps 4(M) x 2(N), warp tile 32 x 64.
// Round 5: software-pipelined double-buffered smem (gmem->reg prefetch of
// tile kt+1 overlaps the MMA phase of tile kt).
//
// Smem layout per tile: t[row][kperm], kperm(k) = (k%4)*8 + k/4, row stride
// 36 words -> LDS.128 fragment loads and STS.128 X stores, conflict-free.
// ---------------------------------------------------------------------------

#define CC 256
#define PAD 36
#define TILEW (128 * PAD)          // 4608 words per tile
#define SMEM_BYTES (4 * TILEW * 4) // 73728 B: Xs[2] + Ws[2]

__device__ __forceinline__ uint32_t f2tf32(float f) {
    uint32_t r;
    asm("cvt.rna.tf32.f32 %0, %1;" : "=r"(r) : "f"(f));
    return r;
}

__device__ __forceinline__ void mma_tf32(float* c, const uint32_t* a, const uint32_t* b) {
    asm volatile(
        "mma.sync.aligned.m16n8k8.row.col.f32.tf32.tf32.f32 "
        "{%0,%1,%2,%3}, {%4,%5,%6,%7}, {%8,%9}, {%0,%1,%2,%3};"
        : "+f"(c[0]), "+f"(c[1]), "+f"(c[2]), "+f"(c[3])
        : "r"(a[0]), "r"(a[1]), "r"(a[2]), "r"(a[3]), "r"(b[0]), "r"(b[1]));
}

struct ConvSet {
    const float* w[4];
    const float* b[4];
    float* out[4];
};

// Shared MMA phase over one 128x128x32 tile pair.
#define MMA_PHASE(Xp, Wp)                                                         \
    {                                                                             \
        _Pragma("unroll") for (int h = 0; h < 2; ++h) {                           \
            uint4 af[2][2], bf[8];                                                \
            _Pragma("unroll") for (int mt = 0; mt < 2; ++mt) {                    \
                int row = wm * 32 + mt * 16 + gp;                                 \
                af[mt][0] = *reinterpret_cast<const uint4*>(                      \
                    &(Xp)[row * PAD + tg * 8 + h * 4]);                           \
                af[mt][1] = *reinterpret_cast<const uint4*>(                      \
                    &(Xp)[(row + 8) * PAD + tg * 8 + h * 4]);                     \
            }                                                                     \
            _Pragma("unroll") for (int nt = 0; nt < 8; ++nt) {                    \
                int col = wn * 64 + nt * 8 + gp;                                  \
                bf[nt] = *reinterpret_cast<const uint4*>(                         \
                    &(Wp)[col * PAD + tg * 8 + h * 4]);                           \
            }                                                                     \
            _Pragma("unroll") for (int s = 0; s < 2; ++s) {                       \
                _Pragma("unroll") for (int mt = 0; mt < 2; ++mt) {                \
                    const uint32_t* a0 = reinterpret_cast<const uint32_t*>(&af[mt][0]); \
                    const uint32_t* a1 = reinterpret_cast<const uint32_t*>(&af[mt][1]); \
                    uint32_t a[4] = {a0[2 * s], a1[2 * s], a0[2 * s + 1], a1[2 * s + 1]}; \
                    _Pragma("unroll") for (int nt = 0; nt < 8; ++nt) {            \
                        const uint32_t* bw = reinterpret_cast<const uint32_t*>(&bf[nt]); \
                        uint32_t bq[2] = {bw[2 * s], bw[2 * s + 1]};              \
                        mma_tf32(acc[mt][nt], a, bq);                             \
                    }                                                             \
                }                                                                 \
            }                                                                     \
        }                                                                         \
    }

// UPS: conv id whose output is 2x nearest-upsampled, or -1.
// grid: (HW/128, nconv*2, B); blockIdx.y = conv*2 + ochHalf.
template <int UPS>
__global__ __launch_bounds__(256) void conv1x1_fused(
    const float* __restrict__ x, ConvSet cs, int HW) {
    extern __shared__ uint32_t sm[];
    uint32_t* Xs[2] = {sm, sm + TILEW};
    uint32_t* Ws[2] = {sm + 2 * TILEW, sm + 3 * TILEW};

    const int tid  = threadIdx.x;
    const int lane = tid & 31;
    const int warp = tid >> 5;
    const int wm = warp >> 1, wn = warp & 1;
    const int tg = lane & 3, gp = lane >> 2;

    const int pt  = blockIdx.x * 128;
    const int cid = blockIdx.y >> 1;
    const int ot  = (blockIdx.y & 1) * 128;
    const int bb  = blockIdx.z;

    const float* xb   = x + (size_t)bb * CC * HW;
    const float* wptr = cs.w[cid];
    const float* bptr = cs.b[cid];
    float* out        = cs.out[cid];

    const int p  = tid & 127;   // pixel within tile (X path)
    const int t7 = tid >> 7;
    const int wo = tid >> 3;    // o base within j-group (W path)
    const int cq = tid & 7;

    float  xr[16];
    float4 wr[4];

    float acc[2][8][4];
#pragma unroll
    for (int mt = 0; mt < 2; ++mt)
#pragma unroll
        for (int nt = 0; nt < 8; ++nt)
#pragma unroll
            for (int i = 0; i < 4; ++i) acc[mt][nt][i] = 0.f;

    auto ldTile = [&](int kt) {
#pragma unroll
        for (int j = 0; j < 4; ++j) {
            int q = 2 * j + t7;
#pragma unroll
            for (int r = 0; r < 4; ++r) {
                int kp = q * 4 + r;
                int k = ((kp & 7) << 2) + (kp >> 3);
                xr[j * 4 + r] = __ldg(&xb[(size_t)(kt * 32 + k) * HW + pt + p]);
            }
        }
#pragma unroll
        for (int j = 0; j < 4; ++j)
            wr[j] = *reinterpret_cast<const float4*>(
                wptr + (size_t)(ot + j * 32 + wo) * CC + kt * 32 + cq * 4);
    };
    auto stTile = [&](int buf) {
        uint32_t* X = Xs[buf];
        uint32_t* W = Ws[buf];
#pragma unroll
        for (int j = 0; j < 4; ++j) {
            int q = 2 * j + t7;
            *reinterpret_cast<uint4*>(&X[p * PAD + q * 4]) =
                make_uint4(f2tf32(xr[j * 4]), f2tf32(xr[j * 4 + 1]),
                           f2tf32(xr[j * 4 + 2]), f2tf32(xr[j * 4 + 3]));
        }
#pragma unroll
        for (int j = 0; j < 4; ++j) {
            int o = j * 32 + wo;
            W[o * PAD + 0 + cq]  = f2tf32(wr[j].x);
            W[o * PAD + 8 + cq]  = f2tf32(wr[j].y);
            W[o * PAD + 16 + cq] = f2tf32(wr[j].z);
            W[o * PAD + 24 + cq] = f2tf32(wr[j].w);
        }
    };

    ldTile(0);
    stTile(0);
    __syncthreads();

    for (int kt = 0; kt < 8; ++kt) {
        if (kt < 7) ldTile(kt + 1);                 // prefetch (latency hidden)
        const uint32_t* X = Xs[kt & 1];
        const uint32_t* W = Ws[kt & 1];
        MMA_PHASE(X, W);
        if (kt < 7) stTile((kt + 1) & 1);
        __syncthreads();
    }

    // ---- epilogue: bias + BHWC store ----
#pragma unroll
    for (int nt = 0; nt < 8; ++nt) {
        int o = ot + wn * 64 + nt * 8 + tg * 2;
        float b0 = __ldg(&bptr[o]);
        float b1 = __ldg(&bptr[o + 1]);
#pragma unroll
        for (int mt = 0; mt < 2; ++mt) {
#pragma unroll
            for (int hr = 0; hr < 2; ++hr) {
                int pg = pt + wm * 32 + mt * 16 + gp + hr * 8;
                float2 r;
                r.x = acc[mt][nt][hr * 2 + 0] + b0;
                r.y = acc[mt][nt][hr * 2 + 1] + b1;
                if (UPS >= 0 && cid == UPS) {
                    int hh = pg >> 6, wc = pg & 63;
                    float* base = out +
                        ((size_t)bb * 16384 + (size_t)(2 * hh) * 128 + 2 * wc) * CC + o;
                    *reinterpret_cast<float2*>(base) = r;
                    *reinterpret_cast<float2*>(base + CC) = r;
                    *reinterpret_cast<float2*>(base + 128 * CC) = r;
                    *reinterpret_cast<float2*>(base + 128 * CC + CC) = r;
                } else {
                    *reinterpret_cast<float2*>(out + ((size_t)bb * HW + pg) * CC + o) = r;
                }
            }
        }
    }
}

// 3x3 stride-2 pad-1 conv, im2col-on-the-fly, pipelined over 72 (kt,tap)
// steps. grid: (32, 2, B).
__global__ __launch_bounds__(256) void conv3x3s2_kernel(
    const float* __restrict__ x, const float* __restrict__ w,
    const float* __restrict__ bias, float* __restrict__ out) {
    extern __shared__ uint32_t sm[];
    uint32_t* Xs[2] = {sm, sm + TILEW};
    uint32_t* Ws[2] = {sm + 2 * TILEW, sm + 3 * TILEW};

    const int tid  = threadIdx.x;
    const int lane = tid & 31;
    const int warp = tid >> 5;
    const int wm = warp >> 1, wn = warp & 1;
    const int tg = lane & 3, gp = lane >> 2;

    const int pt = blockIdx.x * 128;   // output pixel tile in 64x64 grid
    const int ot = blockIdx.y * 128;
    const int bb = blockIdx.z;

    const float* xb = x + (size_t)bb * CC * 16384;

    const int p  = tid & 127;
    const int t7 = tid >> 7;
    const int wo = tid >> 3;
    const int cq = tid & 7;

    const int pg0 = pt + p;
    const int oh = pg0 >> 6, ow = pg0 & 63;

    float xr[16];
    float wr[16];

    float acc[2][8][4];
#pragma unroll
    for (int mt = 0; mt < 2; ++mt)
#pragma unroll
        for (int nt = 0; nt < 8; ++nt)
#pragma unroll
            for (int i = 0; i < 4; ++i) acc[mt][nt][i] = 0.f;

    auto ldTile = [&](int it) {
        int kt = it / 9, tap = it % 9;
        int ti = tap / 3, tj = tap % 3;
        int ih = 2 * oh - 1 + ti;
        int iw = 2 * ow - 1 + tj;
        bool ok = (ih >= 0) && (iw >= 0);
        const float* src = xb + (size_t)(kt * 32) * 16384 + ih * 128 + iw;
#pragma unroll
        for (int j = 0; j < 4; ++j) {
            int q = 2 * j + t7;
#pragma unroll
            for (int r = 0; r < 4; ++r) {
                int kp = q * 4 + r;
                int k = ((kp & 7) << 2) + (kp >> 3);
                xr[j * 4 + r] = ok ? __ldg(src + (size_t)k * 16384) : 0.f;
            }
        }
#pragma unroll
        for (int j = 0; j < 4; ++j) {
            int o = j * 32 + wo;
#pragma unroll
            for (int i = 0; i < 4; ++i)
                wr[j * 4 + i] = __ldg(
                    &w[((size_t)(ot + o) * CC + kt * 32 + cq * 4 + i) * 9 + ti * 3 + tj]);
        }
    };
    auto stTile = [&](int buf) {
        uint32_t* X = Xs[buf];
        uint32_t* W = Ws[buf];
#pragma unroll
        for (int j = 0; j < 4; ++j) {
            int q = 2 * j + t7;
            *reinterpret_cast<uint4*>(&X[p * PAD + q * 4]) =
                make_uint4(f2tf32(xr[j * 4]), f2tf32(xr[j * 4 + 1]),
                           f2tf32(xr[j * 4 + 2]), f2tf32(xr[j * 4 + 3]));
        }
#pragma unroll
        for (int j = 0; j < 4; ++j) {
            int o = j * 32 + wo;
#pragma unroll
            for (int i = 0; i < 4; ++i)
                W[o * PAD + i * 8 + cq] = f2tf32(wr[j * 4 + i]);
        }
    };

    ldTile(0);
    stTile(0);
    __syncthreads();

    for (int it = 0; it < 72; ++it) {
        if (it < 71) ldTile(it + 1);
        const uint32_t* X = Xs[it & 1];
        const uint32_t* W = Ws[it & 1];
        MMA_PHASE(X, W);
        if (it < 71) stTile((it + 1) & 1);
        __syncthreads();
    }

#pragma unroll
    for (int nt = 0; nt < 8; ++nt) {
        int o = ot + wn * 64 + nt * 8 + tg * 2;
        float b0 = __ldg(&bias[o]);
        float b1 = __ldg(&bias[o + 1]);
#pragma unroll
        for (int mt = 0; mt < 2; ++mt) {
#pragma unroll
            for (int hr = 0; hr < 2; ++hr) {
                int pg = pt + wm * 32 + mt * 16 + gp + hr * 8;
                float2 r;
                r.x = acc[mt][nt][hr * 2 + 0] + b0;
                r.y = acc[mt][nt][hr * 2 + 1] + b1;
                *reinterpret_cast<float2*>(out + ((size_t)bb * 4096 + pg) * CC + o) = r;
            }
        }
    }
}

extern "C" void kernel_launch(void* const* d_in, const int* in_sizes, int n_in,
                              void* d_out, int out_size) {
    const float* x1 = (const float*)d_in[0];
    const float* x2 = (const float*)d_in[1];
    const float* q1_w = (const float*)d_in[2];
    const float* q1_b = (const float*)d_in[3];
    const float* q2_w = (const float*)d_in[4];
    const float* q2_b = (const float*)d_in[5];
    const float* ks1_w = (const float*)d_in[6];
    const float* ks1_b = (const float*)d_in[7];
    const float* ks2_w = (const float*)d_in[8];
    const float* ks2_b = (const float*)d_in[9];
    const float* kup_w = (const float*)d_in[10];
    const float* kup_b = (const float*)d_in[11];
    const float* v1_w = (const float*)d_in[12];
    const float* v1_b = (const float*)d_in[13];
    const float* v2_w = (const float*)d_in[14];
    const float* v2_b = (const float*)d_in[15];
    const float* kd_w = (const float*)d_in[16];
    const float* kd_b = (const float*)d_in[17];

    float* out = (float*)d_out;
    float* q1  = out;                    // 2*128*128*256
    float* q2  = out + 8388608;          // 2*64*64*256
    float* kup = out + 10485760;         // 2*128*128*256 (upsampled)
    float* ks1 = out + 18874368;
    float* ks2 = out + 27262976;
    float* kdn = out + 29360128;
    float* v1  = out + 31457280;
    float* v2  = out + 39845888;

    ConvSet cs1;
    cs1.w[0] = q1_w;  cs1.b[0] = q1_b;  cs1.out[0] = q1;
    cs1.w[1] = ks1_w; cs1.b[1] = ks1_b; cs1.out[1] = ks1;
    cs1.w[2] = v1_w;  cs1.b[2] = v1_b;  cs1.out[2] = v1;
    cs1.w[3] = q1_w;  cs1.b[3] = q1_b;  cs1.out[3] = q1;  // unused

    ConvSet cs2;
    cs2.w[0] = q2_w;  cs2.b[0] = q2_b;  cs2.out[0] = q2;
    cs2.w[1] = ks2_w; cs2.b[1] = ks2_b; cs2.out[1] = ks2;
    cs2.w[2] = v2_w;  cs2.b[2] = v2_b;  cs2.out[2] = v2;
    cs2.w[3] = kup_w; cs2.b[3] = kup_b; cs2.out[3] = kup;

    static bool attr_done = false;
    if (!attr_done) {
        cudaFuncSetAttribute(conv1x1_fused<-1>,
                             cudaFuncAttributeMaxDynamicSharedMemorySize, SMEM_BYTES);
        cudaFuncSetAttribute(conv1x1_fused<3>,
                             cudaFuncAttributeMaxDynamicSharedMemorySize, SMEM_BYTES);
        cudaFuncSetAttribute(conv3x3s2_kernel,
                             cudaFuncAttributeMaxDynamicSharedMemorySize, SMEM_BYTES);
        attr_done = true;
    }

    dim3 blk(256);
    conv1x1_fused<-1><<<dim3(128, 6, 2), blk, SMEM_BYTES>>>(x1, cs1, 16384);
    conv1x1_fused<3><<<dim3(32, 8, 2), blk, SMEM_BYTES>>>(x2, cs2, 4096);
    conv3x3s2_kernel<<<dim3(32, 2, 2), blk, SMEM_BYTES>>>(x1, kd_w, kd_b, kdn);
}

// round 6
// speedup vs baseline: 1.8298x; 1.8298x over previous
#include <cuda_runtime.h>
#include <cstdint>

// ---------------------------------------------------------------------------
// FPNAttentionV2: fused conv1x1 batches + conv3x3/s2, BHWC outputs.
// TF32 mma.sync m16n8k8. CTA tile 128 px x (128|64) och x BK=32, 256 thr,
// 8 warps 4(M) x 2(N). launch_bounds(256,2) -> 2 CTAs/SM, inter-CTA overlap
// of load and MMA phases (no register staging, no spills).
//
// Smem: tile[row][kperm], kperm(k) = (k%4)*8 + k/4, row stride 36 words.
// Fragment reads are LDS.128, conflict-free; X stores are STS.128.
// ---------------------------------------------------------------------------

#define CC 256
#define PAD 36

__device__ __forceinline__ uint32_t f2tf32(float f) {
    uint32_t r;
    asm("cvt.rna.tf32.f32 %0, %1;" : "=r"(r) : "f"(f));
    return r;
}

__device__ __forceinline__ void mma_tf32(float* c, const uint32_t* a, const uint32_t* b) {
    asm volatile(
        "mma.sync.aligned.m16n8k8.row.col.f32.tf32.tf32.f32 "
        "{%0,%1,%2,%3}, {%4,%5,%6,%7}, {%8,%9}, {%0,%1,%2,%3};"
        : "+f"(c[0]), "+f"(c[1]), "+f"(c[2]), "+f"(c[3])
        : "r"(a[0]), "r"(a[1]), "r"(a[2]), "r"(a[3]), "r"(b[0]), "r"(b[1]));
}

// One 128 x (NT*16) x 32 tile MMA phase. acc indexed [mt*NT + nt][4].
template <int NT>
__device__ __forceinline__ void mma_phase(
    const uint32_t* __restrict__ Xp, const uint32_t* __restrict__ Wp,
    float (*acc)[4], int wm, int wn, int tg, int gp) {
#pragma unroll
    for (int h = 0; h < 2; ++h) {
        uint4 af[2][2], bf[NT];
#pragma unroll
        for (int mt = 0; mt < 2; ++mt) {
            int row = wm * 32 + mt * 16 + gp;
            af[mt][0] = *reinterpret_cast<const uint4*>(&Xp[row * PAD + tg * 8 + h * 4]);
            af[mt][1] = *reinterpret_cast<const uint4*>(&Xp[(row + 8) * PAD + tg * 8 + h * 4]);
        }
#pragma unroll
        for (int nt = 0; nt < NT; ++nt) {
            int col = wn * (NT * 8) + nt * 8 + gp;
            bf[nt] = *reinterpret_cast<const uint4*>(&Wp[col * PAD + tg * 8 + h * 4]);
        }
#pragma unroll
        for (int s = 0; s < 2; ++s) {
#pragma unroll
            for (int mt = 0; mt < 2; ++mt) {
                const uint32_t* a0 = reinterpret_cast<const uint32_t*>(&af[mt][0]);
                const uint32_t* a1 = reinterpret_cast<const uint32_t*>(&af[mt][1]);
                uint32_t a[4] = {a0[2 * s], a1[2 * s], a0[2 * s + 1], a1[2 * s + 1]};
#pragma unroll
                for (int nt = 0; nt < NT; ++nt) {
                    const uint32_t* bw = reinterpret_cast<const uint32_t*>(&bf[nt]);
                    uint32_t bq[2] = {bw[2 * s], bw[2 * s + 1]};
                    mma_tf32(acc[mt * NT + nt], a, bq);
                }
            }
        }
    }
}

struct ConvSet {
    const float* w[4];
    const float* b[4];
    float* out[4];
};

// UPS: conv id whose output is 2x nearest-upsampled, or -1.
// grid: (HW/128, nconv*2, B); blockIdx.y = conv*2 + ochHalf.
template <int UPS>
__global__ __launch_bounds__(256, 2) void conv1x1_fused(
    const float* __restrict__ x, ConvSet cs, int HW) {
    __shared__ uint32_t Xs[128 * PAD];
    __shared__ uint32_t Ws[128 * PAD];

    const int tid  = threadIdx.x;
    const int lane = tid & 31;
    const int warp = tid >> 5;
    const int wm = warp >> 1, wn = warp & 1;
    const int tg = lane & 3, gp = lane >> 2;

    const int pt  = blockIdx.x * 128;
    const int cid = blockIdx.y >> 1;
    const int ot  = (blockIdx.y & 1) * 128;
    const int bb  = blockIdx.z;

    const float* xb   = x + (size_t)bb * CC * HW;
    const float* wptr = cs.w[cid];
    const float* bptr = cs.b[cid];
    float* out        = cs.out[cid];

    const int p  = tid & 127;
    const int t7 = tid >> 7;
    const int wo = tid >> 3;
    const int cq = tid & 7;

    float acc[16][4];
#pragma unroll
    for (int i = 0; i < 16; ++i)
#pragma unroll
        for (int j = 0; j < 4; ++j) acc[i][j] = 0.f;

    for (int kt = 0; kt < 8; ++kt) {
        // ---- X tile: 32 k x 128 p -> Xs[p][kperm] ----
        float xr[16];
#pragma unroll
        for (int j = 0; j < 4; ++j) {
            int q = 2 * j + t7;
#pragma unroll
            for (int r = 0; r < 4; ++r) {
                int kp = q * 4 + r;
                int k = ((kp & 7) << 2) + (kp >> 3);
                xr[j * 4 + r] = __ldg(&xb[(size_t)(kt * 32 + k) * HW + pt + p]);
            }
        }
        float4 wr[4];
#pragma unroll
        for (int j = 0; j < 4; ++j)
            wr[j] = *reinterpret_cast<const float4*>(
                wptr + (size_t)(ot + j * 32 + wo) * CC + kt * 32 + cq * 4);

#pragma unroll
        for (int j = 0; j < 4; ++j) {
            int q = 2 * j + t7;
            *reinterpret_cast<uint4*>(&Xs[p * PAD + q * 4]) =
                make_uint4(f2tf32(xr[j * 4]), f2tf32(xr[j * 4 + 1]),
                           f2tf32(xr[j * 4 + 2]), f2tf32(xr[j * 4 + 3]));
        }
#pragma unroll
        for (int j = 0; j < 4; ++j) {
            int o = j * 32 + wo;
            Ws[o * PAD + 0 + cq]  = f2tf32(wr[j].x);
            Ws[o * PAD + 8 + cq]  = f2tf32(wr[j].y);
            Ws[o * PAD + 16 + cq] = f2tf32(wr[j].z);
            Ws[o * PAD + 24 + cq] = f2tf32(wr[j].w);
        }
        __syncthreads();

        mma_phase<8>(Xs, Ws, acc, wm, wn, tg, gp);
        __syncthreads();
    }

    // ---- epilogue: bias + BHWC store ----
#pragma unroll
    for (int nt = 0; nt < 8; ++nt) {
        int o = ot + wn * 64 + nt * 8 + tg * 2;
        float b0 = __ldg(&bptr[o]);
        float b1 = __ldg(&bptr[o + 1]);
#pragma unroll
        for (int mt = 0; mt < 2; ++mt) {
#pragma unroll
            for (int hr = 0; hr < 2; ++hr) {
                int pg = pt + wm * 32 + mt * 16 + gp + hr * 8;
                float2 r;
                r.x = acc[mt * 8 + nt][hr * 2 + 0] + b0;
                r.y = acc[mt * 8 + nt][hr * 2 + 1] + b1;
                if (UPS >= 0 && cid == UPS) {
                    int hh = pg >> 6, wc = pg & 63;
                    float* base = out +
                        ((size_t)bb * 16384 + (size_t)(2 * hh) * 128 + 2 * wc) * CC + o;
                    *reinterpret_cast<float2*>(base) = r;
                    *reinterpret_cast<float2*>(base + CC) = r;
                    *reinterpret_cast<float2*>(base + 128 * CC) = r;
                    *reinterpret_cast<float2*>(base + 128 * CC + CC) = r;
                } else {
                    *reinterpret_cast<float2*>(out + ((size_t)bb * HW + pg) * CC + o) = r;
                }
            }
        }
    }
}

// 3x3 stride-2 pad-1 conv, im2col-on-the-fly. CTA tile 128 px x 64 och.
// grid: (32, 4, 2) = 256 CTAs -> fills the chip at 2 CTAs/SM.
__global__ __launch_bounds__(256, 2) void conv3x3s2_kernel(
    const float* __restrict__ x, const float* __restrict__ w,
    const float* __restrict__ bias, float* __restrict__ out) {
    __shared__ uint32_t Xs[128 * PAD];
    __shared__ uint32_t Ws[64 * PAD];

    const int tid  = threadIdx.x;
    const int lane = tid & 31;
    const int warp = tid >> 5;
    const int wm = warp >> 1, wn = warp & 1;
    const int tg = lane & 3, gp = lane >> 2;

    const int pt = blockIdx.x * 128;   // output pixel tile in 64x64 grid
    const int ot = blockIdx.y * 64;
    const int bb = blockIdx.z;

    const float* xb = x + (size_t)bb * CC * 16384;

    const int p  = tid & 127;
    const int t7 = tid >> 7;
    const int wo = tid >> 3;
    const int cq = tid & 7;

    const int pg0 = pt + p;
    const int oh = pg0 >> 6, ow = pg0 & 63;

    float acc[8][4];
#pragma unroll
    for (int i = 0; i < 8; ++i)
#pragma unroll
        for (int j = 0; j < 4; ++j) acc[i][j] = 0.f;

    for (int kt = 0; kt < 8; ++kt) {
        for (int tap = 0; tap < 9; ++tap) {
            int ti = tap / 3, tj = tap % 3;
            int ih = 2 * oh - 1 + ti;
            int iw = 2 * ow - 1 + tj;
            bool ok = (ih >= 0) && (iw >= 0);
            const float* src = xb + (size_t)(kt * 32) * 16384 + ih * 128 + iw;

            float xr[16];
#pragma unroll
            for (int j = 0; j < 4; ++j) {
                int q = 2 * j + t7;
#pragma unroll
                for (int r = 0; r < 4; ++r) {
                    int kp = q * 4 + r;
                    int k = ((kp & 7) << 2) + (kp >> 3);
                    xr[j * 4 + r] = ok ? __ldg(src + (size_t)k * 16384) : 0.f;
                }
            }
            float wrv[8];
#pragma unroll
            for (int j = 0; j < 2; ++j) {
                int o = j * 32 + wo;
#pragma unroll
                for (int i = 0; i < 4; ++i)
                    wrv[j * 4 + i] = __ldg(
                        &w[((size_t)(ot + o) * CC + kt * 32 + cq * 4 + i) * 9 + ti * 3 + tj]);
            }

#pragma unroll
            for (int j = 0; j < 4; ++j) {
                int q = 2 * j + t7;
                *reinterpret_cast<uint4*>(&Xs[p * PAD + q * 4]) =
                    make_uint4(f2tf32(xr[j * 4]), f2tf32(xr[j * 4 + 1]),
                               f2tf32(xr[j * 4 + 2]), f2tf32(xr[j * 4 + 3]));
            }
#pragma unroll
            for (int j = 0; j < 2; ++j) {
                int o = j * 32 + wo;
#pragma unroll
                for (int i = 0; i < 4; ++i)
                    Ws[o * PAD + i * 8 + cq] = f2tf32(wrv[j * 4 + i]);
            }
            __syncthreads();

            mma_phase<4>(Xs, Ws, acc, wm, wn, tg, gp);
            __syncthreads();
        }
    }

#pragma unroll
    for (int nt = 0; nt < 4; ++nt) {
        int o = ot + wn * 32 + nt * 8 + tg * 2;
        float b0 = __ldg(&bias[o]);
        float b1 = __ldg(&bias[o + 1]);
#pragma unroll
        for (int mt = 0; mt < 2; ++mt) {
#pragma unroll
            for (int hr = 0; hr < 2; ++hr) {
                int pg = pt + wm * 32 + mt * 16 + gp + hr * 8;
                float2 r;
                r.x = acc[mt * 4 + nt][hr * 2 + 0] + b0;
                r.y = acc[mt * 4 + nt][hr * 2 + 1] + b1;
                *reinterpret_cast<float2*>(out + ((size_t)bb * 4096 + pg) * CC + o) = r;
            }
        }
    }
}

extern "C" void kernel_launch(void* const* d_in, const int* in_sizes, int n_in,
                              void* d_out, int out_size) {
    const float* x1 = (const float*)d_in[0];
    const float* x2 = (const float*)d_in[1];
    const float* q1_w = (const float*)d_in[2];
    const float* q1_b = (const float*)d_in[3];
    const float* q2_w = (const float*)d_in[4];
    const float* q2_b = (const float*)d_in[5];
    const float* ks1_w = (const float*)d_in[6];
    const float* ks1_b = (const float*)d_in[7];
    const float* ks2_w = (const float*)d_in[8];
    const float* ks2_b = (const float*)d_in[9];
    const float* kup_w = (const float*)d_in[10];
    const float* kup_b = (const float*)d_in[11];
    const float* v1_w = (const float*)d_in[12];
    const float* v1_b = (const float*)d_in[13];
    const float* v2_w = (const float*)d_in[14];
    const float* v2_b = (const float*)d_in[15];
    const float* kd_w = (const float*)d_in[16];
    const float* kd_b = (const float*)d_in[17];

    float* out = (float*)d_out;
    float* q1  = out;                    // 2*128*128*256
    float* q2  = out + 8388608;          // 2*64*64*256
    float* kup = out + 10485760;         // 2*128*128*256 (upsampled)
    float* ks1 = out + 18874368;
    float* ks2 = out + 27262976;
    float* kdn = out + 29360128;
    float* v1  = out + 31457280;
    float* v2  = out + 39845888;

    ConvSet cs1;
    cs1.w[0] = q1_w;  cs1.b[0] = q1_b;  cs1.out[0] = q1;
    cs1.w[1] = ks1_w; cs1.b[1] = ks1_b; cs1.out[1] = ks1;
    cs1.w[2] = v1_w;  cs1.b[2] = v1_b;  cs1.out[2] = v1;
    cs1.w[3] = q1_w;  cs1.b[3] = q1_b;  cs1.out[3] = q1;  // unused

    ConvSet cs2;
    cs2.w[0] = q2_w;  cs2.b[0] = q2_b;  cs2.out[0] = q2;
    cs2.w[1] = ks2_w; cs2.b[1] = ks2_b; cs2.out[1] = ks2;
    cs2.w[2] = v2_w;  cs2.b[2] = v2_b;  cs2.out[2] = v2;
    cs2.w[3] = kup_w; cs2.b[3] = kup_b; cs2.out[3] = kup;

    dim3 blk(256);
    conv1x1_fused<-1><<<dim3(128, 6, 2), blk>>>(x1, cs1, 16384);
    conv1x1_fused<3><<<dim3(32, 8, 2), blk>>>(x2, cs2, 4096);
    conv3x3s2_kernel<<<dim3(32, 4, 2), blk>>>(x1, kd_w, kd_b, kdn);
}